// round 12
// baseline (speedup 1.0000x reference)
#include <cuda_runtime.h>
#include <cuda_fp16.h>

#define RGRID 128
#define NSTEPS 128
#define NV (RGRID*RGRID*RGRID)

// fp16 color grid: 32 halves (64 B) per voxel, 64-B aligned.
__device__ __align__(16) __half g_grid16[(size_t)NV * 32];
// paired sigma: g_sigpair[v] = (sigma[v], sigma[v+1])
__device__ __align__(16) __half2 g_sigpair[(size_t)NV];

__device__ __forceinline__ unsigned pk(float a, float b) {
    __half2 h = __floats2half2_rn(a, b);
    return *reinterpret_cast<unsigned*>(&h);
}
__device__ __forceinline__ __half2 u2h(unsigned u) {
    return *reinterpret_cast<__half2*>(&u);
}

// sigmoid via MUFU.TANH: 1 XU op instead of EX2 + full-precision division
__device__ __forceinline__ float sigmoid_t(float x) {
    float t;
    asm("tanh.approx.f32 %0, %1;" : "=f"(t) : "f"(x * 0.5f));
    return fmaf(0.5f, t, 0.5f);
}

// One float4 (= 4 channels) per thread; 7 threads per voxel. Coalesced reads.
// j==6 thread also builds the sigma pair.
__global__ void __launch_bounds__(256) convert_kernel(const float* __restrict__ grid) {
    int i = blockIdx.x * blockDim.x + threadIdx.x;
    if (i >= NV * 7) return;
    int v = i / 7;
    int j = i - v * 7;

    float4 f = __ldg(reinterpret_cast<const float4*>(grid) + i);

    uint2 q = make_uint2(pk(f.x, f.y), pk(f.z, f.w));
    *reinterpret_cast<uint2*>(g_grid16 + (size_t)v * 32 + j * 4) = q;

    if (j == 6) {
        int vn = (v + 1 < NV) ? v + 1 : v;
        float sn = __ldg(grid + (size_t)vn * 28 + 27);
        g_sigpair[v] = __floats2half2_rn(f.w, sn);   // (sigma[v], sigma[v+1])
    }
}

__device__ __forceinline__ float gsum8(float v, unsigned m) {
    v += __shfl_xor_sync(m, v, 1);
    v += __shfl_xor_sync(m, v, 2);
    v += __shfl_xor_sync(m, v, 4);
    return v;
}

// packed half2 8-lane-group sum
__device__ __forceinline__ __half2 gsum8h2(__half2 v, unsigned gm) {
#pragma unroll
    for (int d = 1; d < 8; d <<= 1) {
        unsigned u = __shfl_xor_sync(gm, *reinterpret_cast<unsigned*>(&v), d);
        v = __hadd2(v, *reinterpret_cast<__half2*>(&u));
    }
    return v;
}

__global__ void __launch_bounds__(128, 10) octree_render_kernel(
    const float* __restrict__ rays_o,
    const float* __restrict__ rays_d,
    const float* __restrict__ scaling,
    const float* __restrict__ offset,
    float* __restrict__ out,
    int N)
{
    int tid  = blockIdx.x * blockDim.x + threadIdx.x;
    int ray  = tid >> 3;          // 8 lanes per ray
    int c    = tid & 7;           // corner id: bit2=dx, bit1=dy, bit0=dz
    if (ray >= N) return;

    int lane = threadIdx.x & 31;
    unsigned gmask = 0xFFu << (lane & 24);

    float rox = rays_o[3*ray+0], roy = rays_o[3*ray+1], roz = rays_o[3*ray+2];
    float rdx = rays_d[3*ray+0], rdy = rays_d[3*ray+1], rdz = rays_d[3*ray+2];

    float inv_n = rsqrtf(rdx*rdx + rdy*rdy + rdz*rdz);
    float ux = rdx*inv_n, uy = rdy*inv_n, uz = rdz*inv_n;

    float sx = scaling[0], sy = scaling[1], sz = scaling[2];
    float fx = offset[0],  fy = offset[1],  fz = offset[2];

    float ox = rox*sx + fx, oy = roy*sy + fy, oz = roz*sz + fz;
    float dx = ux*sx, dy = uy*sy, dz = uz*sz;

    float dlen = sqrtf(dx*dx + dy*dy + dz*dz);
    float delta_scale = 1.0f/dlen;

    float ivx = 1.0f/((fabsf(dx) > 1e-9f) ? dx : 1e-9f);
    float ivy = 1.0f/((fabsf(dy) > 1e-9f) ? dy : 1e-9f);
    float ivz = 1.0f/((fabsf(dz) > 1e-9f) ? dz : 1e-9f);

    float t1x = (0.0f - ox)*ivx, t2x = (1.0f - ox)*ivx;
    float t1y = (0.0f - oy)*ivy, t2y = (1.0f - oy)*ivy;
    float t1z = (0.0f - oz)*ivz, t2z = (1.0f - oz)*ivz;

    float tlo = fmaxf(fmaxf(fminf(t1x,t2x), fminf(t1y,t2y)), fminf(t1z,t2z));
    float thi = fminf(fminf(fmaxf(t1x,t2x), fmaxf(t1y,t2y)), fmaxf(t1z,t2z));
    float tmin = fmaxf(tlo, 0.0f);

    float T = 1.0f, cr = 0.0f, cg = 0.0f, cb = 0.0f;

    if (thi > tmin) {
        float dt   = (thi - tmin) * (1.0f/(float)NSTEPS);
        float dtds = dt * delta_scale;

        const float C0 = 0.28209479177387814f;
        const float C1 = 0.4886025119029199f;
        float b0 = C0;
        float b1 = -C1*uy;
        float b2 =  C1*uz;
        float b3 = -C1*ux;
        float b4 =  1.0925484305920792f*ux*uy;
        float b5 = -1.0925484305920792f*uy*uz;
        float b6 =  0.31539156525252005f*(2.0f*uz*uz - ux*ux - uy*uy);
        float b7 = -1.0925484305920792f*ux*uz;
        float b8 =  0.5462742152960396f*(ux*ux - uy*uy);

        __half2 B0  = __floats2half2_rn(b0, b1);
        __half2 B1  = __floats2half2_rn(b2, b3);
        __half2 B2  = __floats2half2_rn(b4, b5);
        __half2 B3  = __floats2half2_rn(b6, b7);
        __half2 B4  = __floats2half2_rn(b8, b0);
        __half2 B5  = __floats2half2_rn(b1, b2);
        __half2 B6  = __floats2half2_rn(b3, b4);
        __half2 B7  = __floats2half2_rn(b5, b6);
        __half2 B8  = __floats2half2_rn(b7, b8);
        __half2 B13 = __floats2half2_rn(b8, 0.0f);

        int cx = (c >> 2) & 1, cy = (c >> 1) & 1, cz = c & 1;
        int coff = (cx << 14) + (cy << 7) + cz;

        float oxR = fmaf(ox, (float)RGRID, -0.5f);
        float oyR = fmaf(oy, (float)RGRID, -0.5f);
        float ozR = fmaf(oz, (float)RGRID, -0.5f);
        float dxR = dx*(float)RGRID, dyR = dy*(float)RGRID, dzR = dz*(float)RGRID;

        bool finished = false;
        for (int s0 = 0; s0 < NSTEPS && !finished; s0 += 8) {
            // ---- sigma phase: lane c owns step s0+c, full trilerp alone ----
            float t  = tmin + ((float)(s0 + c) + 0.5f)*dt;
            float px = fminf(fmaxf(fmaf(t, dxR, oxR), 0.0f), 126.9999f);
            float py = fminf(fmaxf(fmaf(t, dyR, oyR), 0.0f), 126.9999f);
            float pz = fminf(fmaxf(fmaf(t, dzR, ozR), 0.0f), 126.9999f);
            float gx = floorf(px), gy = floorf(py), gz = floorf(pz);
            int ix = (int)gx, iy = (int)gy, iz = (int)gz;
            float wxx = px - gx, wyy = py - gy, wzz = pz - gz;

            int cell = (ix << 14) + (iy << 7) + iz;
            __half2 p00 = __ldg(g_sigpair + cell);
            __half2 p01 = __ldg(g_sigpair + cell + (1 << 7));
            __half2 p10 = __ldg(g_sigpair + cell + (1 << 14));
            __half2 p11 = __ldg(g_sigpair + cell + (1 << 14) + (1 << 7));
            float2 f00 = __half22float2(p00);
            float2 f01 = __half22float2(p01);
            float2 f10 = __half22float2(p10);
            float2 f11 = __half22float2(p11);

            float ax = 1.0f - wxx, ay = 1.0f - wyy;
            float w00 = ax*ay, w01 = ax*wyy, w10 = wxx*ay, w11 = wxx*wyy;
            float sz0 = w00*f00.x + w01*f01.x + w10*f10.x + w11*f11.x;
            float sz1 = w00*f00.y + w01*f01.y + w10*f10.y + w11*f11.y;
            float sig_own = fmaf(wzz, sz1 - sz0, sz0);

            unsigned bal = __ballot_sync(gmask, sig_own > 0.0f);
            unsigned m = (bal >> (lane & 24)) & 0xFFu;

            // ---- color phase: only active steps ----
            while (m) {
                int j = __ffs(m) - 1; m &= m - 1;
                float sgj   = __shfl_sync(gmask, sig_own, j, 8);
                int   cellj = __shfl_sync(gmask, cell,    j, 8);
                float vx    = __shfl_sync(gmask, wxx,     j, 8);
                float vy    = __shfl_sync(gmask, wyy,     j, 8);
                float vz    = __shfl_sync(gmask, wzz,     j, 8);

                int vi = cellj + coff;
                float wc = (cx ? vx : 1.0f - vx)
                         * (cy ? vy : 1.0f - vy)
                         * (cz ? vz : 1.0f - vz);

                const uint4* p = reinterpret_cast<const uint4*>(g_grid16 + ((size_t)vi << 5));
                uint4 q0 = __ldg(p+0);
                uint4 q1 = __ldg(p+1);
                uint4 q2 = __ldg(p+2);
                uint2 q3 = __ldg(reinterpret_cast<const uint2*>(p+3));

                __half2 h0  = u2h(q0.x), h1  = u2h(q0.y), h2  = u2h(q0.z), h3  = u2h(q0.w);
                __half2 h4  = u2h(q1.x), h5  = u2h(q1.y), h6  = u2h(q1.z), h7  = u2h(q1.w);
                __half2 h8  = u2h(q2.x), h9  = u2h(q2.y), h10 = u2h(q2.z), h11 = u2h(q2.w);
                __half2 h12 = u2h(q3.x), h13 = u2h(q3.y);

                __half2 accA = __hfma2(h1, B1, __hmul2(h0, B0));
                accA = __hfma2(h2, B2, accA);
                accA = __hfma2(h3, B3, accA);
                __half2 t4   = __hmul2(h4, B4);            // (c8*b8 | c9*b0)
                __half2 accB = __hfma2(h6, B6, __hmul2(h5, B5));
                accB = __hfma2(h7, B7, accB);
                accB = __hfma2(h8, B8, accB);
                __half2 accC = __hfma2(h10, B1, __hmul2(h9, B0));
                accC = __hfma2(h11, B2, accC);
                accC = __hfma2(h12, B3, accC);
                __half2 t13  = __hmul2(h13, B13);          // (c26*b8 | 0)

                float2 fA = __half22float2(accA);
                float2 f4 = __half22float2(t4);
                float2 fB = __half22float2(accB);
                float2 fC = __half22float2(accC);
                float d0 = fA.x + fA.y + f4.x;
                float d1 = fB.x + fB.y + f4.y;
                float d2 = fC.x + fC.y + __low2float(t13);

                __half2 pe = gsum8h2(__floats2half2_rn(wc * d0, wc * d1), gmask);
                float e2 = gsum8(wc * d2, gmask);
                float2 e01 = __half22float2(pe);

                // alpha = 1 - exp(-y), y = sg*dtds <= ~0.007 (3rd-order; err ~1e-10)
                float y = sgj*dtds;
                float alpha = y*fmaf(-0.5f*y, fmaf(-(1.0f/3.0f), y, 1.0f), 1.0f);
                float c0 = sigmoid_t(e01.x);
                float c1 = sigmoid_t(e01.y);
                float c2 = sigmoid_t(e2);

                float Ta = T*alpha;
                cr = fmaf(Ta, c0, cr);
                cg = fmaf(Ta, c1, cg);
                cb = fmaf(Ta, c2, cb);
                T  = T*(1.0f - alpha);
                if (T < 1e-4f) { finished = true; break; }  // group-uniform
            }
        }
    }

    if (c == 0) {
        out[3*ray+0] = fmaf(T, 1.0f, cr);
        out[3*ray+1] = fmaf(T, 1.0f, cg);
        out[3*ray+2] = fmaf(T, 1.0f, cb);
    }
}

extern "C" void kernel_launch(void* const* d_in, const int* in_sizes, int n_in,
                              void* d_out, int out_size) {
    const float* rays_o  = (const float*)d_in[0];
    const float* rays_d  = (const float*)d_in[1];
    const float* grid    = (const float*)d_in[2];
    const float* scaling = (const float*)d_in[3];
    const float* offset  = (const float*)d_in[4];
    float* out = (float*)d_out;

    int convN = NV * 7;
    convert_kernel<<<(convN + 255) / 256, 256>>>(grid);

    int N = in_sizes[0] / 3;
    int threads_total = N * 8;
    int block = 128;
    int blocks = (threads_total + block - 1) / block;
    octree_render_kernel<<<blocks, block>>>(rays_o, rays_d, scaling, offset, out, N);
}

// round 13
// speedup vs baseline: 1.0341x; 1.0341x over previous
#include <cuda_runtime.h>
#include <cuda_fp16.h>

#define RGRID 128
#define NSTEPS 128
#define NV (RGRID*RGRID*RGRID)

// fp16 color grid: 32 halves (64 B) per voxel, 64-B aligned.
__device__ __align__(16) __half g_grid16[(size_t)NV * 32];
// paired sigma: g_sigpair[v] = (sigma[v], sigma[v+1])
__device__ __align__(16) __half2 g_sigpair[(size_t)NV];
// persistent-kernel ray work queue
__device__ unsigned g_ray_ctr;

__device__ __forceinline__ unsigned pk(float a, float b) {
    __half2 h = __floats2half2_rn(a, b);
    return *reinterpret_cast<unsigned*>(&h);
}
__device__ __forceinline__ __half2 u2h(unsigned u) {
    return *reinterpret_cast<__half2*>(&u);
}

// sigmoid via MUFU.TANH
__device__ __forceinline__ float sigmoid_t(float x) {
    float t;
    asm("tanh.approx.f32 %0, %1;" : "=f"(t) : "f"(x * 0.5f));
    return fmaf(0.5f, t, 0.5f);
}

// One float4 (= 4 channels) per thread; 7 threads per voxel. Coalesced reads.
// j==6 thread also builds the sigma pair. Thread 0 resets the ray queue.
__global__ void __launch_bounds__(256) convert_kernel(const float* __restrict__ grid) {
    int i = blockIdx.x * blockDim.x + threadIdx.x;
    if (i == 0) g_ray_ctr = 0u;
    if (i >= NV * 7) return;
    int v = i / 7;
    int j = i - v * 7;

    float4 f = __ldg(reinterpret_cast<const float4*>(grid) + i);

    uint2 q = make_uint2(pk(f.x, f.y), pk(f.z, f.w));
    *reinterpret_cast<uint2*>(g_grid16 + (size_t)v * 32 + j * 4) = q;

    if (j == 6) {
        int vn = (v + 1 < NV) ? v + 1 : v;
        float sn = __ldg(grid + (size_t)vn * 28 + 27);
        g_sigpair[v] = __floats2half2_rn(f.w, sn);   // (sigma[v], sigma[v+1])
    }
}

__device__ __forceinline__ float gsum8(float v, unsigned m) {
    v += __shfl_xor_sync(m, v, 1);
    v += __shfl_xor_sync(m, v, 2);
    v += __shfl_xor_sync(m, v, 4);
    return v;
}

__device__ __forceinline__ __half2 gsum8h2(__half2 v, unsigned gm) {
#pragma unroll
    for (int d = 1; d < 8; d <<= 1) {
        unsigned u = __shfl_xor_sync(gm, *reinterpret_cast<unsigned*>(&v), d);
        v = __hadd2(v, *reinterpret_cast<__half2*>(&u));
    }
    return v;
}

__global__ void __launch_bounds__(128, 10) octree_render_kernel(
    const float* __restrict__ rays_o,
    const float* __restrict__ rays_d,
    const float* __restrict__ scaling,
    const float* __restrict__ offset,
    float* __restrict__ out,
    int N)
{
    int c    = threadIdx.x & 7;   // corner id: bit2=dx, bit1=dy, bit0=dz
    int lane = threadIdx.x & 31;
    unsigned gmask = 0xFFu << (lane & 24);

    float sx = scaling[0], sy = scaling[1], sz = scaling[2];
    float fx = offset[0],  fy = offset[1],  fz = offset[2];

    int cx = (c >> 2) & 1, cy = (c >> 1) & 1, cz = c & 1;
    int coff = (cx << 14) + (cy << 7) + cz;

    // persistent loop: pull rays from the global queue
    for (;;) {
        unsigned rfetch = 0;
        if (c == 0) rfetch = atomicAdd(&g_ray_ctr, 1u);
        unsigned ray = __shfl_sync(gmask, rfetch, 0, 8);
        if (ray >= (unsigned)N) break;

        float rox = rays_o[3*ray+0], roy = rays_o[3*ray+1], roz = rays_o[3*ray+2];
        float rdx = rays_d[3*ray+0], rdy = rays_d[3*ray+1], rdz = rays_d[3*ray+2];

        float inv_n = rsqrtf(rdx*rdx + rdy*rdy + rdz*rdz);
        float ux = rdx*inv_n, uy = rdy*inv_n, uz = rdz*inv_n;

        float ox = rox*sx + fx, oy = roy*sy + fy, oz = roz*sz + fz;
        float dx = ux*sx, dy = uy*sy, dz = uz*sz;

        float dlen = sqrtf(dx*dx + dy*dy + dz*dz);
        float delta_scale = 1.0f/dlen;

        float ivx = 1.0f/((fabsf(dx) > 1e-9f) ? dx : 1e-9f);
        float ivy = 1.0f/((fabsf(dy) > 1e-9f) ? dy : 1e-9f);
        float ivz = 1.0f/((fabsf(dz) > 1e-9f) ? dz : 1e-9f);

        float t1x = (0.0f - ox)*ivx, t2x = (1.0f - ox)*ivx;
        float t1y = (0.0f - oy)*ivy, t2y = (1.0f - oy)*ivy;
        float t1z = (0.0f - oz)*ivz, t2z = (1.0f - oz)*ivz;

        float tlo = fmaxf(fmaxf(fminf(t1x,t2x), fminf(t1y,t2y)), fminf(t1z,t2z));
        float thi = fminf(fminf(fmaxf(t1x,t2x), fmaxf(t1y,t2y)), fmaxf(t1z,t2z));
        float tmin = fmaxf(tlo, 0.0f);

        float T = 1.0f, cr = 0.0f, cg = 0.0f, cb = 0.0f;

        if (thi > tmin) {
            float dt   = (thi - tmin) * (1.0f/(float)NSTEPS);
            float dtds = dt * delta_scale;

            const float C0 = 0.28209479177387814f;
            const float C1 = 0.4886025119029199f;
            float b0 = C0;
            float b1 = -C1*uy;
            float b2 =  C1*uz;
            float b3 = -C1*ux;
            float b4 =  1.0925484305920792f*ux*uy;
            float b5 = -1.0925484305920792f*uy*uz;
            float b6 =  0.31539156525252005f*(2.0f*uz*uz - ux*ux - uy*uy);
            float b7 = -1.0925484305920792f*ux*uz;
            float b8 =  0.5462742152960396f*(ux*ux - uy*uy);

            __half2 B0  = __floats2half2_rn(b0, b1);
            __half2 B1  = __floats2half2_rn(b2, b3);
            __half2 B2  = __floats2half2_rn(b4, b5);
            __half2 B3  = __floats2half2_rn(b6, b7);
            __half2 B4  = __floats2half2_rn(b8, b0);
            __half2 B5  = __floats2half2_rn(b1, b2);
            __half2 B6  = __floats2half2_rn(b3, b4);
            __half2 B7  = __floats2half2_rn(b5, b6);
            __half2 B8  = __floats2half2_rn(b7, b8);
            __half2 B13 = __floats2half2_rn(b8, 0.0f);

            float oxR = fmaf(ox, (float)RGRID, -0.5f);
            float oyR = fmaf(oy, (float)RGRID, -0.5f);
            float ozR = fmaf(oz, (float)RGRID, -0.5f);
            float dxR = dx*(float)RGRID, dyR = dy*(float)RGRID, dzR = dz*(float)RGRID;

            bool finished = false;
            for (int s0 = 0; s0 < NSTEPS && !finished; s0 += 8) {
                // ---- sigma phase: lane c owns step s0+c ----
                float t  = tmin + ((float)(s0 + c) + 0.5f)*dt;
                float px = fminf(fmaxf(fmaf(t, dxR, oxR), 0.0f), 126.9999f);
                float py = fminf(fmaxf(fmaf(t, dyR, oyR), 0.0f), 126.9999f);
                float pz = fminf(fmaxf(fmaf(t, dzR, ozR), 0.0f), 126.9999f);
                float gx = floorf(px), gy = floorf(py), gz = floorf(pz);
                int ix = (int)gx, iy = (int)gy, iz = (int)gz;
                float wxx = px - gx, wyy = py - gy, wzz = pz - gz;

                int cell = (ix << 14) + (iy << 7) + iz;
                __half2 p00 = __ldg(g_sigpair + cell);
                __half2 p01 = __ldg(g_sigpair + cell + (1 << 7));
                __half2 p10 = __ldg(g_sigpair + cell + (1 << 14));
                __half2 p11 = __ldg(g_sigpair + cell + (1 << 14) + (1 << 7));
                float2 f00 = __half22float2(p00);
                float2 f01 = __half22float2(p01);
                float2 f10 = __half22float2(p10);
                float2 f11 = __half22float2(p11);

                float ax = 1.0f - wxx, ay = 1.0f - wyy;
                float w00 = ax*ay, w01 = ax*wyy, w10 = wxx*ay, w11 = wxx*wyy;
                float sz0 = w00*f00.x + w01*f01.x + w10*f10.x + w11*f11.x;
                float sz1 = w00*f00.y + w01*f01.y + w10*f10.y + w11*f11.y;
                float sig_own = fmaf(wzz, sz1 - sz0, sz0);

                unsigned bal = __ballot_sync(gmask, sig_own > 0.0f);
                unsigned m = (bal >> (lane & 24)) & 0xFFu;

                // ---- color phase: only active steps ----
                while (m) {
                    int j = __ffs(m) - 1; m &= m - 1;
                    float sgj   = __shfl_sync(gmask, sig_own, j, 8);
                    int   cellj = __shfl_sync(gmask, cell,    j, 8);
                    float vx    = __shfl_sync(gmask, wxx,     j, 8);
                    float vy    = __shfl_sync(gmask, wyy,     j, 8);
                    float vz    = __shfl_sync(gmask, wzz,     j, 8);

                    int vi = cellj + coff;
                    float wc = (cx ? vx : 1.0f - vx)
                             * (cy ? vy : 1.0f - vy)
                             * (cz ? vz : 1.0f - vz);

                    const uint4* p = reinterpret_cast<const uint4*>(g_grid16 + ((size_t)vi << 5));
                    uint4 q0 = __ldg(p+0);
                    uint4 q1 = __ldg(p+1);
                    uint4 q2 = __ldg(p+2);
                    uint2 q3 = __ldg(reinterpret_cast<const uint2*>(p+3));

                    __half2 h0  = u2h(q0.x), h1  = u2h(q0.y), h2  = u2h(q0.z), h3  = u2h(q0.w);
                    __half2 h4  = u2h(q1.x), h5  = u2h(q1.y), h6  = u2h(q1.z), h7  = u2h(q1.w);
                    __half2 h8  = u2h(q2.x), h9  = u2h(q2.y), h10 = u2h(q2.z), h11 = u2h(q2.w);
                    __half2 h12 = u2h(q3.x), h13 = u2h(q3.y);

                    __half2 accA = __hfma2(h1, B1, __hmul2(h0, B0));
                    accA = __hfma2(h2, B2, accA);
                    accA = __hfma2(h3, B3, accA);
                    __half2 t4   = __hmul2(h4, B4);
                    __half2 accB = __hfma2(h6, B6, __hmul2(h5, B5));
                    accB = __hfma2(h7, B7, accB);
                    accB = __hfma2(h8, B8, accB);
                    __half2 accC = __hfma2(h10, B1, __hmul2(h9, B0));
                    accC = __hfma2(h11, B2, accC);
                    accC = __hfma2(h12, B3, accC);
                    __half2 t13  = __hmul2(h13, B13);

                    float2 fA = __half22float2(accA);
                    float2 f4 = __half22float2(t4);
                    float2 fB = __half22float2(accB);
                    float2 fC = __half22float2(accC);
                    float d0 = fA.x + fA.y + f4.x;
                    float d1 = fB.x + fB.y + f4.y;
                    float d2 = fC.x + fC.y + __low2float(t13);

                    __half2 pe = gsum8h2(__floats2half2_rn(wc * d0, wc * d1), gmask);
                    float e2 = gsum8(wc * d2, gmask);
                    float2 e01 = __half22float2(pe);

                    // alpha = 1 - exp(-y), y small (3rd-order; err ~1e-10)
                    float y = sgj*dtds;
                    float alpha = y*fmaf(-0.5f*y, fmaf(-(1.0f/3.0f), y, 1.0f), 1.0f);
                    float c0 = sigmoid_t(e01.x);
                    float c1 = sigmoid_t(e01.y);
                    float c2 = sigmoid_t(e2);

                    float Ta = T*alpha;
                    cr = fmaf(Ta, c0, cr);
                    cg = fmaf(Ta, c1, cg);
                    cb = fmaf(Ta, c2, cb);
                    T  = T*(1.0f - alpha);
                    if (T < 1e-4f) { finished = true; break; }
                }
            }
        }

        if (c == 0) {
            out[3*ray+0] = fmaf(T, 1.0f, cr);
            out[3*ray+1] = fmaf(T, 1.0f, cg);
            out[3*ray+2] = fmaf(T, 1.0f, cb);
        }
    }
}

extern "C" void kernel_launch(void* const* d_in, const int* in_sizes, int n_in,
                              void* d_out, int out_size) {
    const float* rays_o  = (const float*)d_in[0];
    const float* rays_d  = (const float*)d_in[1];
    const float* grid    = (const float*)d_in[2];
    const float* scaling = (const float*)d_in[3];
    const float* offset  = (const float*)d_in[4];
    float* out = (float*)d_out;

    int convN = NV * 7;
    convert_kernel<<<(convN + 255) / 256, 256>>>(grid);

    int N = in_sizes[0] / 3;
    // one resident wave: 152 SMs x 10 blocks/SM
    int blocks = 152 * 10;
    octree_render_kernel<<<blocks, 128>>>(rays_o, rays_d, scaling, offset, out, N);
}

// round 14
// speedup vs baseline: 1.0556x; 1.0208x over previous
#include <cuda_runtime.h>
#include <cuda_fp16.h>

#define RGRID 128
#define NSTEPS 128
#define NV (RGRID*RGRID*RGRID)

// fp16 color grid: 32 halves (64 B) per voxel, 64-B aligned.
__device__ __align__(16) __half g_grid16[(size_t)NV * 32];
// paired sigma: g_sigpair[v] = (sigma[v], sigma[v+1])
__device__ __align__(16) __half2 g_sigpair[(size_t)NV];
// persistent-kernel ray work queue
__device__ unsigned g_ray_ctr;

__device__ __forceinline__ unsigned pk(float a, float b) {
    __half2 h = __floats2half2_rn(a, b);
    return *reinterpret_cast<unsigned*>(&h);
}
__device__ __forceinline__ __half2 u2h(unsigned u) {
    return *reinterpret_cast<__half2*>(&u);
}

__device__ __forceinline__ float sigmoid_t(float x) {
    float t;
    asm("tanh.approx.f32 %0, %1;" : "=f"(t) : "f"(x * 0.5f));
    return fmaf(0.5f, t, 0.5f);
}

// One float4 (= 4 channels) per thread; 7 threads per voxel. Coalesced reads.
// j==6 thread also builds the sigma pair. Thread 0 resets the ray queue.
__global__ void __launch_bounds__(256) convert_kernel(const float* __restrict__ grid) {
    int i = blockIdx.x * blockDim.x + threadIdx.x;
    if (i == 0) g_ray_ctr = 0u;
    if (i >= NV * 7) return;
    int v = i / 7;
    int j = i - v * 7;

    float4 f = __ldg(reinterpret_cast<const float4*>(grid) + i);

    uint2 q = make_uint2(pk(f.x, f.y), pk(f.z, f.w));
    *reinterpret_cast<uint2*>(g_grid16 + (size_t)v * 32 + j * 4) = q;

    if (j == 6) {
        int vn = (v + 1 < NV) ? v + 1 : v;
        float sn = __ldg(grid + (size_t)vn * 28 + 27);
        g_sigpair[v] = __floats2half2_rn(f.w, sn);
    }
}

__device__ __forceinline__ float gsum8(float v, unsigned m) {
    v += __shfl_xor_sync(m, v, 1);
    v += __shfl_xor_sync(m, v, 2);
    v += __shfl_xor_sync(m, v, 4);
    return v;
}

__device__ __forceinline__ __half2 gsum8h2(__half2 v, unsigned gm) {
#pragma unroll
    for (int d = 1; d < 8; d <<= 1) {
        unsigned u = __shfl_xor_sync(gm, *reinterpret_cast<unsigned*>(&v), d);
        v = __hadd2(v, *reinterpret_cast<__half2*>(&u));
    }
    return v;
}

__global__ void __launch_bounds__(128, 8) octree_render_kernel(
    const float* __restrict__ rays_o,
    const float* __restrict__ rays_d,
    const float* __restrict__ scaling,
    const float* __restrict__ offset,
    float* __restrict__ out,
    int N)
{
    int c    = threadIdx.x & 7;   // corner id: bit2=dx, bit1=dy, bit0=dz
    int lane = threadIdx.x & 31;
    unsigned gmask = 0xFFu << (lane & 24);

    float sx = scaling[0], sy = scaling[1], sz = scaling[2];
    float fx = offset[0],  fy = offset[1],  fz = offset[2];

    int cx = (c >> 2) & 1, cy = (c >> 1) & 1, cz = c & 1;
    int coff = (cx << 14) + (cy << 7) + cz;

    for (;;) {
        unsigned rfetch = 0;
        if (c == 0) rfetch = atomicAdd(&g_ray_ctr, 1u);
        unsigned ray = __shfl_sync(gmask, rfetch, 0, 8);
        if (ray >= (unsigned)N) break;

        float rox = rays_o[3*ray+0], roy = rays_o[3*ray+1], roz = rays_o[3*ray+2];
        float rdx = rays_d[3*ray+0], rdy = rays_d[3*ray+1], rdz = rays_d[3*ray+2];

        float inv_n = rsqrtf(rdx*rdx + rdy*rdy + rdz*rdz);
        float ux = rdx*inv_n, uy = rdy*inv_n, uz = rdz*inv_n;

        float ox = rox*sx + fx, oy = roy*sy + fy, oz = roz*sz + fz;
        float dx = ux*sx, dy = uy*sy, dz = uz*sz;

        float dlen = sqrtf(dx*dx + dy*dy + dz*dz);
        float delta_scale = 1.0f/dlen;

        float ivx = 1.0f/((fabsf(dx) > 1e-9f) ? dx : 1e-9f);
        float ivy = 1.0f/((fabsf(dy) > 1e-9f) ? dy : 1e-9f);
        float ivz = 1.0f/((fabsf(dz) > 1e-9f) ? dz : 1e-9f);

        float t1x = (0.0f - ox)*ivx, t2x = (1.0f - ox)*ivx;
        float t1y = (0.0f - oy)*ivy, t2y = (1.0f - oy)*ivy;
        float t1z = (0.0f - oz)*ivz, t2z = (1.0f - oz)*ivz;

        float tlo = fmaxf(fmaxf(fminf(t1x,t2x), fminf(t1y,t2y)), fminf(t1z,t2z));
        float thi = fminf(fminf(fmaxf(t1x,t2x), fmaxf(t1y,t2y)), fmaxf(t1z,t2z));
        float tmin = fmaxf(tlo, 0.0f);

        float T = 1.0f, cr = 0.0f, cg = 0.0f, cb = 0.0f;

        if (thi > tmin) {
            float dt   = (thi - tmin) * (1.0f/(float)NSTEPS);
            float dtds = dt * delta_scale;

            const float C0 = 0.28209479177387814f;
            const float C1 = 0.4886025119029199f;
            float b0 = C0;
            float b1 = -C1*uy;
            float b2 =  C1*uz;
            float b3 = -C1*ux;
            float b4 =  1.0925484305920792f*ux*uy;
            float b5 = -1.0925484305920792f*uy*uz;
            float b6 =  0.31539156525252005f*(2.0f*uz*uz - ux*ux - uy*uy);
            float b7 = -1.0925484305920792f*ux*uz;
            float b8 =  0.5462742152960396f*(ux*ux - uy*uy);

            __half2 B0  = __floats2half2_rn(b0, b1);
            __half2 B1  = __floats2half2_rn(b2, b3);
            __half2 B2  = __floats2half2_rn(b4, b5);
            __half2 B3  = __floats2half2_rn(b6, b7);
            __half2 B4  = __floats2half2_rn(b8, b0);
            __half2 B5  = __floats2half2_rn(b1, b2);
            __half2 B6  = __floats2half2_rn(b3, b4);
            __half2 B7  = __floats2half2_rn(b5, b6);
            __half2 B8  = __floats2half2_rn(b7, b8);
            __half2 B13 = __floats2half2_rn(b8, 0.0f);

            float oxR = fmaf(ox, (float)RGRID, -0.5f);
            float oyR = fmaf(oy, (float)RGRID, -0.5f);
            float ozR = fmaf(oz, (float)RGRID, -0.5f);
            float dxR = dx*(float)RGRID, dyR = dy*(float)RGRID, dzR = dz*(float)RGRID;

            bool finished = false;
            for (int s0 = 0; s0 < NSTEPS && !finished; s0 += 8) {
                // ---- sigma phase: lane c owns step s0+c ----
                float t  = tmin + ((float)(s0 + c) + 0.5f)*dt;
                float px = fminf(fmaxf(fmaf(t, dxR, oxR), 0.0f), 126.9999f);
                float py = fminf(fmaxf(fmaf(t, dyR, oyR), 0.0f), 126.9999f);
                float pz = fminf(fmaxf(fmaf(t, dzR, ozR), 0.0f), 126.9999f);
                float gx = floorf(px), gy = floorf(py), gz = floorf(pz);
                int ix = (int)gx, iy = (int)gy, iz = (int)gz;
                float wxx = px - gx, wyy = py - gy, wzz = pz - gz;

                int cell = (ix << 14) + (iy << 7) + iz;
                __half2 p00 = __ldg(g_sigpair + cell);
                __half2 p01 = __ldg(g_sigpair + cell + (1 << 7));
                __half2 p10 = __ldg(g_sigpair + cell + (1 << 14));
                __half2 p11 = __ldg(g_sigpair + cell + (1 << 14) + (1 << 7));
                float2 f00 = __half22float2(p00);
                float2 f01 = __half22float2(p01);
                float2 f10 = __half22float2(p10);
                float2 f11 = __half22float2(p11);

                float ax = 1.0f - wxx, ay = 1.0f - wyy;
                float w00 = ax*ay, w01 = ax*wyy, w10 = wxx*ay, w11 = wxx*wyy;
                float sz0 = w00*f00.x + w01*f01.x + w10*f10.x + w11*f11.x;
                float sz1 = w00*f00.y + w01*f01.y + w10*f10.y + w11*f11.y;
                float sig_own = fmaf(wzz, sz1 - sz0, sz0);

                unsigned bal = __ballot_sync(gmask, sig_own > 0.0f);
                unsigned m = (bal >> (lane & 24)) & 0xFFu;

                // ---- color phase: 2-deep pipelined over active steps ----
                if (m) {
                    // prologue: state + loads for first active step
                    int j = __ffs(m) - 1; m &= m - 1;
                    float sgj = __shfl_sync(gmask, sig_own, j, 8);
                    int   cl  = __shfl_sync(gmask, cell,    j, 8);
                    float vx  = __shfl_sync(gmask, wxx,     j, 8);
                    float vy  = __shfl_sync(gmask, wyy,     j, 8);
                    float vz  = __shfl_sync(gmask, wzz,     j, 8);
                    float wc  = (cx ? vx : 1.0f - vx)
                              * (cy ? vy : 1.0f - vy)
                              * (cz ? vz : 1.0f - vz);
                    const uint4* p = reinterpret_cast<const uint4*>(
                        g_grid16 + ((size_t)(cl + coff) << 5));
                    uint4 q0 = __ldg(p+0);
                    uint4 q1 = __ldg(p+1);
                    uint4 q2 = __ldg(p+2);
                    uint2 q3 = __ldg(reinterpret_cast<const uint2*>(p+3));

                    for (;;) {
                        // dots for current step (consumes q*)
                        __half2 h0  = u2h(q0.x), h1  = u2h(q0.y), h2  = u2h(q0.z), h3  = u2h(q0.w);
                        __half2 h4  = u2h(q1.x), h5  = u2h(q1.y), h6  = u2h(q1.z), h7  = u2h(q1.w);
                        __half2 h8  = u2h(q2.x), h9  = u2h(q2.y), h10 = u2h(q2.z), h11 = u2h(q2.w);
                        __half2 h12 = u2h(q3.x), h13 = u2h(q3.y);

                        __half2 accA = __hfma2(h1, B1, __hmul2(h0, B0));
                        accA = __hfma2(h2, B2, accA);
                        accA = __hfma2(h3, B3, accA);
                        __half2 t4   = __hmul2(h4, B4);
                        __half2 accB = __hfma2(h6, B6, __hmul2(h5, B5));
                        accB = __hfma2(h7, B7, accB);
                        accB = __hfma2(h8, B8, accB);
                        __half2 accC = __hfma2(h10, B1, __hmul2(h9, B0));
                        accC = __hfma2(h11, B2, accC);
                        accC = __hfma2(h12, B3, accC);
                        __half2 t13  = __hmul2(h13, B13);

                        float2 fA = __half22float2(accA);
                        float2 f4 = __half22float2(t4);
                        float2 fB = __half22float2(accB);
                        float2 fC = __half22float2(accC);
                        float d0 = fA.x + fA.y + f4.x;
                        float d1 = fB.x + fB.y + f4.y;
                        float d2 = fC.x + fC.y + __low2float(t13);

                        // prefetch next active step BEFORE the serial reduction
                        bool have_next = (m != 0);
                        float sg2 = 0.0f, wc2 = 0.0f;
                        uint4 r0, r1, r2; uint2 r3;
                        if (have_next) {
                            int j2 = __ffs(m) - 1; m &= m - 1;
                            sg2 = __shfl_sync(gmask, sig_own, j2, 8);
                            int   cl2 = __shfl_sync(gmask, cell, j2, 8);
                            float nx  = __shfl_sync(gmask, wxx,  j2, 8);
                            float ny  = __shfl_sync(gmask, wyy,  j2, 8);
                            float nz  = __shfl_sync(gmask, wzz,  j2, 8);
                            wc2 = (cx ? nx : 1.0f - nx)
                                * (cy ? ny : 1.0f - ny)
                                * (cz ? nz : 1.0f - nz);
                            const uint4* p2 = reinterpret_cast<const uint4*>(
                                g_grid16 + ((size_t)(cl2 + coff) << 5));
                            r0 = __ldg(p2+0);
                            r1 = __ldg(p2+1);
                            r2 = __ldg(p2+2);
                            r3 = __ldg(reinterpret_cast<const uint2*>(p2+3));
                        }

                        // serial reduction + epilogue for current (overlaps next loads)
                        __half2 pe = gsum8h2(__floats2half2_rn(wc * d0, wc * d1), gmask);
                        float e2 = gsum8(wc * d2, gmask);
                        float2 e01 = __half22float2(pe);

                        float y = sgj*dtds;
                        float alpha = y*fmaf(-0.5f*y, fmaf(-(1.0f/3.0f), y, 1.0f), 1.0f);
                        float c0 = sigmoid_t(e01.x);
                        float c1 = sigmoid_t(e01.y);
                        float c2 = sigmoid_t(e2);

                        float Ta = T*alpha;
                        cr = fmaf(Ta, c0, cr);
                        cg = fmaf(Ta, c1, cg);
                        cb = fmaf(Ta, c2, cb);
                        T  = T*(1.0f - alpha);
                        if (T < 1e-4f) { finished = true; break; }
                        if (!have_next) break;

                        sgj = sg2; wc = wc2;
                        q0 = r0; q1 = r1; q2 = r2; q3 = r3;
                    }
                }
            }
        }

        if (c == 0) {
            out[3*ray+0] = fmaf(T, 1.0f, cr);
            out[3*ray+1] = fmaf(T, 1.0f, cg);
            out[3*ray+2] = fmaf(T, 1.0f, cb);
        }
    }
}

extern "C" void kernel_launch(void* const* d_in, const int* in_sizes, int n_in,
                              void* d_out, int out_size) {
    const float* rays_o  = (const float*)d_in[0];
    const float* rays_d  = (const float*)d_in[1];
    const float* grid    = (const float*)d_in[2];
    const float* scaling = (const float*)d_in[3];
    const float* offset  = (const float*)d_in[4];
    float* out = (float*)d_out;

    int convN = NV * 7;
    convert_kernel<<<(convN + 255) / 256, 256>>>(grid);

    int N = in_sizes[0] / 3;
    // one resident wave at 8 blocks/SM
    int blocks = 152 * 8;
    octree_render_kernel<<<blocks, 128>>>(rays_o, rays_d, scaling, offset, out, N);
}

// round 16
// speedup vs baseline: 1.5046x; 1.4254x over previous
#include <cuda_runtime.h>
#include <cuda_fp16.h>

#define RGRID 128
#define NSTEPS 128
#define NV (RGRID*RGRID*RGRID)

// int8 color grid: 32 B per voxel = 27 x int8 coeffs, 1 pad, half scale, 2 pad.
__device__ __align__(16) unsigned g_grid8[(size_t)NV * 8];
// paired sigma: g_sigpair[v] = (sigma[v], sigma[v+1])
__device__ __align__(16) __half2 g_sigpair[(size_t)NV];
// persistent-kernel ray work queue
__device__ unsigned g_ray_ctr;

__device__ __forceinline__ float sigmoid_t(float x) {
    float t;
    asm("tanh.approx.f32 %0, %1;" : "=f"(t) : "f"(x * 0.5f));
    return fmaf(0.5f, t, 0.5f);
}

// signed int8 dp4a (SASS IDP.4A.S8.S8)
__device__ __forceinline__ int dp4a_s(int a, int b, int c) {
    int r;
    asm("dp4a.s32.s32 %0, %1, %2, %3;" : "=r"(r) : "r"(a), "r"(b), "r"(c));
    return r;
}

__device__ __forceinline__ unsigned q4(float a, float b, float c, float d, float qs) {
    int ia = __float2int_rn(a * qs), ib = __float2int_rn(b * qs);
    int ic = __float2int_rn(c * qs), id = __float2int_rn(d * qs);
    return (unsigned)(ia & 0xFF) | ((unsigned)(ib & 0xFF) << 8)
         | ((unsigned)(ic & 0xFF) << 16) | ((unsigned)(id & 0xFF) << 24);
}
__device__ __forceinline__ int pk4i(int a, int b, int c, int d) {
    return (int)((unsigned)(a & 0xFF) | ((unsigned)(b & 0xFF) << 8)
         | ((unsigned)(c & 0xFF) << 16) | ((unsigned)(d & 0xFF) << 24));
}

// One thread per voxel; smem-staged coalesced reads. 128 voxels per block.
__global__ void __launch_bounds__(128) convert_kernel(const float* __restrict__ grid) {
    __shared__ float s[128 * 28];
    int tid = threadIdx.x;
    int v0  = blockIdx.x * 128;
    if (blockIdx.x == 0 && tid == 0) g_ray_ctr = 0u;

    // cooperative coalesced load: 128 voxels x 7 float4
    const float4* src4 = reinterpret_cast<const float4*>(grid) + (size_t)v0 * 7;
    float4* s4 = reinterpret_cast<float4*>(s);
#pragma unroll
    for (int k = 0; k < 7; k++)
        s4[tid + k * 128] = __ldg(src4 + tid + k * 128);
    __syncthreads();

    int v = v0 + tid;
    const float4* c4 = s4 + tid * 7;
    float4 f0 = c4[0], f1 = c4[1], f2 = c4[2], f3 = c4[3];
    float4 f4v = c4[4], f5 = c4[5], f6 = c4[6];

    // max |coeff| over channels 0..26 (f6.w is sigma)
    float ma = 1e-8f;
    ma = fmaxf(ma, fmaxf(fmaxf(fabsf(f0.x), fabsf(f0.y)), fmaxf(fabsf(f0.z), fabsf(f0.w))));
    ma = fmaxf(ma, fmaxf(fmaxf(fabsf(f1.x), fabsf(f1.y)), fmaxf(fabsf(f1.z), fabsf(f1.w))));
    ma = fmaxf(ma, fmaxf(fmaxf(fabsf(f2.x), fabsf(f2.y)), fmaxf(fabsf(f2.z), fabsf(f2.w))));
    ma = fmaxf(ma, fmaxf(fmaxf(fabsf(f3.x), fabsf(f3.y)), fmaxf(fabsf(f3.z), fabsf(f3.w))));
    ma = fmaxf(ma, fmaxf(fmaxf(fabsf(f4v.x), fabsf(f4v.y)), fmaxf(fabsf(f4v.z), fabsf(f4v.w))));
    ma = fmaxf(ma, fmaxf(fmaxf(fabsf(f5.x), fabsf(f5.y)), fmaxf(fabsf(f5.z), fabsf(f5.w))));
    ma = fmaxf(ma, fmaxf(fabsf(f6.x), fmaxf(fabsf(f6.y), fabsf(f6.z))));

    float qs = 127.0f / ma;
    uint4 oa, ob;
    oa.x = q4(f0.x, f0.y, f0.z, f0.w, qs);
    oa.y = q4(f1.x, f1.y, f1.z, f1.w, qs);
    oa.z = q4(f2.x, f2.y, f2.z, f2.w, qs);
    oa.w = q4(f3.x, f3.y, f3.z, f3.w, qs);
    ob.x = q4(f4v.x, f4v.y, f4v.z, f4v.w, qs);
    ob.y = q4(f5.x, f5.y, f5.z, f5.w, qs);
    ob.z = q4(f6.x, f6.y, f6.z, 0.0f, qs);
    ob.w = (unsigned)__half_as_ushort(__float2half(ma * (1.0f / 127.0f)));

    uint4* dst = reinterpret_cast<uint4*>(g_grid8 + (size_t)v * 8);
    dst[0] = oa; dst[1] = ob;

    // sigma pair
    float sig = f6.w;
    float sign;
    if (tid < 127) sign = s[(tid + 1) * 28 + 27];
    else {
        int vn = (v + 1 < NV) ? v + 1 : v;
        sign = __ldg(grid + (size_t)vn * 28 + 27);
    }
    g_sigpair[v] = __floats2half2_rn(sig, sign);
}

__device__ __forceinline__ float gsum8(float v, unsigned m) {
    v += __shfl_xor_sync(m, v, 1);
    v += __shfl_xor_sync(m, v, 2);
    v += __shfl_xor_sync(m, v, 4);
    return v;
}

__device__ __forceinline__ __half2 gsum8h2(__half2 v, unsigned gm) {
#pragma unroll
    for (int d = 1; d < 8; d <<= 1) {
        unsigned u = __shfl_xor_sync(gm, *reinterpret_cast<unsigned*>(&v), d);
        v = __hadd2(v, *reinterpret_cast<__half2*>(&u));
    }
    return v;
}

__global__ void __launch_bounds__(128, 8) octree_render_kernel(
    const float* __restrict__ rays_o,
    const float* __restrict__ rays_d,
    const float* __restrict__ scaling,
    const float* __restrict__ offset,
    float* __restrict__ out,
    int N)
{
    int c    = threadIdx.x & 7;   // corner id: bit2=dx, bit1=dy, bit0=dz
    int lane = threadIdx.x & 31;
    unsigned gmask = 0xFFu << (lane & 24);

    float sx = scaling[0], sy = scaling[1], sz = scaling[2];
    float fx = offset[0],  fy = offset[1],  fz = offset[2];

    int cx = (c >> 2) & 1, cy = (c >> 1) & 1, cz = c & 1;
    int coff = (cx << 14) + (cy << 7) + cz;

    for (;;) {
        unsigned rfetch = 0;
        if (c == 0) rfetch = atomicAdd(&g_ray_ctr, 1u);
        unsigned ray = __shfl_sync(gmask, rfetch, 0, 8);
        if (ray >= (unsigned)N) break;

        float rox = rays_o[3*ray+0], roy = rays_o[3*ray+1], roz = rays_o[3*ray+2];
        float rdx = rays_d[3*ray+0], rdy = rays_d[3*ray+1], rdz = rays_d[3*ray+2];

        float inv_n = rsqrtf(rdx*rdx + rdy*rdy + rdz*rdz);
        float ux = rdx*inv_n, uy = rdy*inv_n, uz = rdz*inv_n;

        float ox = rox*sx + fx, oy = roy*sy + fy, oz = roz*sz + fz;
        float dx = ux*sx, dy = uy*sy, dz = uz*sz;

        float dlen = sqrtf(dx*dx + dy*dy + dz*dz);
        float delta_scale = 1.0f/dlen;

        float ivx = 1.0f/((fabsf(dx) > 1e-9f) ? dx : 1e-9f);
        float ivy = 1.0f/((fabsf(dy) > 1e-9f) ? dy : 1e-9f);
        float ivz = 1.0f/((fabsf(dz) > 1e-9f) ? dz : 1e-9f);

        float t1x = (0.0f - ox)*ivx, t2x = (1.0f - ox)*ivx;
        float t1y = (0.0f - oy)*ivy, t2y = (1.0f - oy)*ivy;
        float t1z = (0.0f - oz)*ivz, t2z = (1.0f - oz)*ivz;

        float tlo = fmaxf(fmaxf(fminf(t1x,t2x), fminf(t1y,t2y)), fminf(t1z,t2z));
        float thi = fminf(fminf(fmaxf(t1x,t2x), fmaxf(t1y,t2y)), fmaxf(t1z,t2z));
        float tmin = fmaxf(tlo, 0.0f);

        float T = 1.0f, cr = 0.0f, cg = 0.0f, cb = 0.0f;

        if (thi > tmin) {
            float dt   = (thi - tmin) * (1.0f/(float)NSTEPS);
            float dtds = dt * delta_scale;

            const float C0 = 0.28209479177387814f;
            const float C1 = 0.4886025119029199f;
            float b0 = C0;
            float b1 = -C1*uy;
            float b2 =  C1*uz;
            float b3 = -C1*ux;
            float b4 =  1.0925484305920792f*ux*uy;
            float b5 = -1.0925484305920792f*uy*uz;
            float b6 =  0.31539156525252005f*(2.0f*uz*uz - ux*ux - uy*uy);
            float b7 = -1.0925484305920792f*ux*uz;
            float b8 =  0.5462742152960396f*(ux*ux - uy*uy);

            // quantize basis to int8 once per ray
            float bmax = fmaxf(fabsf(b0), fmaxf(fabsf(b1), fmaxf(fabsf(b2),
                         fmaxf(fabsf(b3), fmaxf(fabsf(b4), fmaxf(fabsf(b5),
                         fmaxf(fabsf(b6), fmaxf(fabsf(b7), fabsf(b8)))))))));
            float bq = 127.0f / bmax;
            int q0 = __float2int_rn(b0*bq), q1 = __float2int_rn(b1*bq), q2 = __float2int_rn(b2*bq);
            int q3 = __float2int_rn(b3*bq), q4i = __float2int_rn(b4*bq), q5 = __float2int_rn(b5*bq);
            int q6 = __float2int_rn(b6*bq), q7 = __float2int_rn(b7*bq), q8 = __float2int_rn(b8*bq);

            int Bw0  = pk4i(q0, q1, q2, q3);
            int Bw1  = pk4i(q4i, q5, q6, q7);
            int Bw2A = pk4i(q8, 0, 0, 0);
            int Bw2B = pk4i(0, q0, q1, q2);
            int Bw3  = pk4i(q3, q4i, q5, q6);
            int Bw4A = pk4i(q7, q8, 0, 0);
            int Bw4B = pk4i(0, 0, q0, q1);
            int Bw5  = pk4i(q2, q3, q4i, q5);
            int Bw6  = pk4i(q6, q7, q8, 0);
            float rB = bmax * (1.0f / 127.0f);

            float oxR = fmaf(ox, (float)RGRID, -0.5f);
            float oyR = fmaf(oy, (float)RGRID, -0.5f);
            float ozR = fmaf(oz, (float)RGRID, -0.5f);
            float dxR = dx*(float)RGRID, dyR = dy*(float)RGRID, dzR = dz*(float)RGRID;

            bool finished = false;
            for (int s0 = 0; s0 < NSTEPS && !finished; s0 += 8) {
                // ---- sigma phase: lane c owns step s0+c ----
                float t  = tmin + ((float)(s0 + c) + 0.5f)*dt;
                float px = fminf(fmaxf(fmaf(t, dxR, oxR), 0.0f), 126.9999f);
                float py = fminf(fmaxf(fmaf(t, dyR, oyR), 0.0f), 126.9999f);
                float pz = fminf(fmaxf(fmaf(t, dzR, ozR), 0.0f), 126.9999f);
                float gx = floorf(px), gy = floorf(py), gz = floorf(pz);
                int ix = (int)gx, iy = (int)gy, iz = (int)gz;
                float wxx = px - gx, wyy = py - gy, wzz = pz - gz;

                int cell = (ix << 14) + (iy << 7) + iz;
                __half2 p00 = __ldg(g_sigpair + cell);
                __half2 p01 = __ldg(g_sigpair + cell + (1 << 7));
                __half2 p10 = __ldg(g_sigpair + cell + (1 << 14));
                __half2 p11 = __ldg(g_sigpair + cell + (1 << 14) + (1 << 7));
                float2 f00 = __half22float2(p00);
                float2 f01 = __half22float2(p01);
                float2 f10 = __half22float2(p10);
                float2 f11 = __half22float2(p11);

                float ax = 1.0f - wxx, ay = 1.0f - wyy;
                float w00 = ax*ay, w01 = ax*wyy, w10 = wxx*ay, w11 = wxx*wyy;
                float sz0 = w00*f00.x + w01*f01.x + w10*f10.x + w11*f11.x;
                float sz1 = w00*f00.y + w01*f01.y + w10*f10.y + w11*f11.y;
                float sig_own = fmaf(wzz, sz1 - sz0, sz0);

                unsigned bal = __ballot_sync(gmask, sig_own > 0.0f);
                unsigned m = (bal >> (lane & 24)) & 0xFFu;

                // ---- color phase: 2-deep pipelined over active steps ----
                if (m) {
                    int j = __ffs(m) - 1; m &= m - 1;
                    float sgj = __shfl_sync(gmask, sig_own, j, 8);
                    int   cl  = __shfl_sync(gmask, cell,    j, 8);
                    float vx  = __shfl_sync(gmask, wxx,     j, 8);
                    float vy  = __shfl_sync(gmask, wyy,     j, 8);
                    float vz  = __shfl_sync(gmask, wzz,     j, 8);
                    float wc  = (cx ? vx : 1.0f - vx)
                              * (cy ? vy : 1.0f - vy)
                              * (cz ? vz : 1.0f - vz);
                    const uint4* p = reinterpret_cast<const uint4*>(
                        g_grid8 + ((size_t)(cl + coff) << 3));
                    uint4 qa = __ldg(p+0);
                    uint4 qb = __ldg(p+1);

                    for (;;) {
                        // signed int8 dots for current step
                        int d0i = dp4a_s((int)qa.x, Bw0, dp4a_s((int)qa.y, Bw1, dp4a_s((int)qa.z, Bw2A, 0)));
                        int d1i = dp4a_s((int)qa.z, Bw2B, dp4a_s((int)qa.w, Bw3, dp4a_s((int)qb.x, Bw4A, 0)));
                        int d2i = dp4a_s((int)qb.x, Bw4B, dp4a_s((int)qb.y, Bw5, dp4a_s((int)qb.z, Bw6, 0)));
                        float svf = __half2float(__ushort_as_half((unsigned short)(qb.w & 0xFFFFu)));
                        float fv = svf * wc;
                        float d0 = fv * (float)d0i;
                        float d1 = fv * (float)d1i;
                        float d2 = fv * (float)d2i;

                        // prefetch next active step BEFORE the serial reduction
                        bool have_next = (m != 0);
                        float sg2 = 0.0f, wc2 = 0.0f;
                        uint4 ra, rb;
                        if (have_next) {
                            int j2 = __ffs(m) - 1; m &= m - 1;
                            sg2 = __shfl_sync(gmask, sig_own, j2, 8);
                            int   cl2 = __shfl_sync(gmask, cell, j2, 8);
                            float nx  = __shfl_sync(gmask, wxx,  j2, 8);
                            float ny  = __shfl_sync(gmask, wyy,  j2, 8);
                            float nz  = __shfl_sync(gmask, wzz,  j2, 8);
                            wc2 = (cx ? nx : 1.0f - nx)
                                * (cy ? ny : 1.0f - ny)
                                * (cz ? nz : 1.0f - nz);
                            const uint4* p2 = reinterpret_cast<const uint4*>(
                                g_grid8 + ((size_t)(cl2 + coff) << 3));
                            ra = __ldg(p2+0);
                            rb = __ldg(p2+1);
                        }

                        // serial reduction + epilogue (overlaps next loads)
                        __half2 pe = gsum8h2(__floats2half2_rn(d0, d1), gmask);
                        float e2r = gsum8(d2, gmask);
                        float2 e01 = __half22float2(pe);

                        float y = sgj*dtds;
                        float alpha = y*fmaf(-0.5f*y, fmaf(-(1.0f/3.0f), y, 1.0f), 1.0f);
                        float c0 = sigmoid_t(e01.x * rB);
                        float c1 = sigmoid_t(e01.y * rB);
                        float c2 = sigmoid_t(e2r * rB);

                        float Ta = T*alpha;
                        cr = fmaf(Ta, c0, cr);
                        cg = fmaf(Ta, c1, cg);
                        cb = fmaf(Ta, c2, cb);
                        T  = T*(1.0f - alpha);
                        if (T < 1e-4f) { finished = true; break; }
                        if (!have_next) break;

                        sgj = sg2; wc = wc2;
                        qa = ra; qb = rb;
                    }
                }
            }
        }

        if (c == 0) {
            out[3*ray+0] = fmaf(T, 1.0f, cr);
            out[3*ray+1] = fmaf(T, 1.0f, cg);
            out[3*ray+2] = fmaf(T, 1.0f, cb);
        }
    }
}

extern "C" void kernel_launch(void* const* d_in, const int* in_sizes, int n_in,
                              void* d_out, int out_size) {
    const float* rays_o  = (const float*)d_in[0];
    const float* rays_d  = (const float*)d_in[1];
    const float* grid    = (const float*)d_in[2];
    const float* scaling = (const float*)d_in[3];
    const float* offset  = (const float*)d_in[4];
    float* out = (float*)d_out;

    // NV voxels / 128 per block
    convert_kernel<<<NV / 128, 128>>>(grid);

    int N = in_sizes[0] / 3;
    int blocks = 152 * 8;   // one resident wave at 8 blocks/SM
    octree_render_kernel<<<blocks, 128>>>(rays_o, rays_d, scaling, offset, out, N);
}